// round 7
// baseline (speedup 1.0000x reference)
#include <cuda_runtime.h>
#include <cuda_bf16.h>
#include <stdint.h>

#define NCLS 6
#define HDIM 512
#define WDIM 512
#define NB   8
#define NPIX (NB * HDIM * WDIM)   // 2097152
#define IMG  (HDIM * WDIM)        // 262144

#define TH 16                      // rows produced per edge block
#define SHROWS (TH + 10)           // 26 (5-row halo each side)
#define PAD 8                      // zero pad on each side of the 512 cols
#define SWB (WDIM + 2 * PAD)       // 528 bytes per padded row

// Packed per-pixel byte: bits[2:0] = label, bit 3 = edge flag.
__device__ unsigned char g_le[NPIX];
// Global accumulators (zero at module load; finalizing block resets them
// after writing out, so graph replays stay deterministic).
__device__ double g_accA;              // sum over all pixels of lp_label
__device__ double g_accB;              // sum over edge pixels of lp_sum
__device__ double g_accC;              // sum over edge pixels of lp_label
__device__ unsigned long long g_accE;  // edge pixel count
__device__ unsigned int g_done;        // completed-block counter

// Kernel 1: one block per (batch, 16-row band). Full-width 512-col strips:
// int4-coalesced loads, byte smem, branch-free sliding-window sums.
__global__ void __launch_bounds__(256) ls_edge_kernel(const int* __restrict__ target) {
    __shared__ unsigned char sT[SHROWS][SWB];   // labels (0..5), padded
    __shared__ unsigned char sH[SHROWS][WDIM];  // horizontal 11-window sums (<=55)

    const int bx = blockIdx.x;           // 0 .. 255
    const int b = bx >> 5;               // batch
    const int band = bx & 31;            // 16-row band
    const int y0 = band * TH;
    const int tid = threadIdx.x;
    const int* timg = target + (size_t)b * IMG;

    // Zero the horizontal pads (26 rows x 16 pad bytes = 104 uint writes).
    if (tid < SHROWS * 4) {
        const int r = tid >> 2, q = tid & 3;
        // pads: bytes [0,8) and [520,528) -> 4 uints per row
        unsigned int* prow = reinterpret_cast<unsigned int*>(&sT[r][0]);
        const int off = (q < 2) ? q : (128 + q);  // uint index 0,1,130,131
        prow[off] = 0u;
    }

    // Load 26 rows x 512 ints as int4, pack to bytes. 26*128 = 3328 int4s.
    for (int idx = tid; idx < SHROWS * 128; idx += 256) {
        const int r = idx >> 7;           // 0..25
        const int seg = idx & 127;        // int4 index within row
        const int gy = y0 + r - 5;
        uchar4 pk = make_uchar4(0, 0, 0, 0);
        if (gy >= 0 && gy < HDIM) {
            const int4 t = *reinterpret_cast<const int4*>(&timg[gy * WDIM + seg * 4]);
            pk = make_uchar4((unsigned char)t.x, (unsigned char)t.y,
                             (unsigned char)t.z, (unsigned char)t.w);
        }
        *reinterpret_cast<uchar4*>(&sT[r][PAD + seg * 4]) = pk;
    }
    __syncthreads();

    // Horizontal sliding sums: 26 rows x 4 segments of 128 cols = 104 units.
    if (tid < SHROWS * 4) {
        const int r = tid >> 2;
        const int c0 = (tid & 3) * 128;
        // window for output c: padded cols c+3 .. c+13
        int s = 0;
#pragma unroll
        for (int d = 0; d < 11; d++) s += sT[r][c0 + 3 + d];
        sH[r][c0] = (unsigned char)s;
        for (int c = c0 + 1; c < c0 + 128; c++) {
            s += (int)sT[r][c + 13] - (int)sT[r][c + 2];
            sH[r][c] = (unsigned char)s;
        }
    }
    __syncthreads();

    // Vertical sliding sums + pack: each thread owns 2 adjacent columns.
    {
        const int c = tid * 2;
        int S0 = 0, S1 = 0;
#pragma unroll
        for (int d = 0; d < 11; d++) { S0 += sH[d][c]; S1 += sH[d][c + 1]; }
        unsigned char* obase = &g_le[(size_t)b * IMG + y0 * WDIM + c];
#pragma unroll
        for (int r = 0; r < TH; r++) {
            if (r > 0) {
                S0 += (int)sH[r + 10][c] - (int)sH[r - 1][c];
                S1 += (int)sH[r + 10][c + 1] - (int)sH[r - 1][c + 1];
            }
            const int l0 = sT[r + 5][PAD + c];
            const int l1 = sT[r + 5][PAD + c + 1];
            uchar2 pk;
            pk.x = (unsigned char)(l0 | ((121 * l0 != S0) ? 8 : 0));
            pk.y = (unsigned char)(l1 | ((121 * l1 != S1) ? 8 : 0));
            *reinterpret_cast<uchar2*>(obase + r * WDIM) = pk;
        }
    }
}

// Kernel 2: main (R3-proven shape: 4 px/thread, float4 streaming loads).
// Last block finalizes and resets state for graph replay.
__global__ void __launch_bounds__(256) ls_main_kernel(const float* __restrict__ x,
                                                      float* __restrict__ out) {
    const int tix = blockIdx.x * blockDim.x + threadIdx.x;  // 0 .. NPIX/4-1
    const int base = tix << 2;                               // pixel index, mult of 4
    const int b = base >> 18;                                // / 262144
    const int rem = base & (IMG - 1);                        // h*512 + w

    // Packed label|edge bytes (L2-resident from kernel 1).
    const uchar4 le4 = *reinterpret_cast<const uchar4*>(&g_le[base]);
    const unsigned int le[4] = {le4.x, le4.y, le4.z, le4.w};

    // 6 channels x 4 pixels as float4, streaming (read-once data).
    const float* xb = x + (size_t)b * (NCLS * IMG) + rem;
    float v[NCLS][4];
#pragma unroll
    for (int c = 0; c < NCLS; c++) {
        float4 t = __ldcs(reinterpret_cast<const float4*>(&xb[(size_t)c * IMG]));
        v[c][0] = t.x; v[c][1] = t.y; v[c][2] = t.z; v[c][3] = t.w;
    }

    float tA = 0.f, tB = 0.f, tC = 0.f;
    int tE = 0;
#pragma unroll
    for (int j = 0; j < 4; j++) {
        const int lab = (int)(le[j] & 7u);
        // x ~ N(0,1): exp() cannot overflow; skip max-subtraction.
        float se = 0.f, sumx = 0.f, xl = 0.f;
#pragma unroll
        for (int c = 0; c < NCLS; c++) {
            float vc = v[c][j];
            se += __expf(vc);
            sumx += vc;
            xl = (lab == c) ? vc : xl;  // predicated select
        }
        float lse = __logf(se);
        float lpl = xl - lse;            // log_p at the label
        float lps = sumx - 6.0f * lse;   // sum over classes of log_p

        tA += lpl;
        if (le[j] & 8u) { tE++; tB += lps; tC += lpl; }
    }

    // Block reduction
#pragma unroll
    for (int off = 16; off > 0; off >>= 1) {
        tA += __shfl_down_sync(0xffffffffu, tA, off);
        tB += __shfl_down_sync(0xffffffffu, tB, off);
        tC += __shfl_down_sync(0xffffffffu, tC, off);
        tE += __shfl_down_sync(0xffffffffu, tE, off);
    }

    __shared__ float sA[8], sB[8], sC[8];
    __shared__ int sE[8];
    const int warp = threadIdx.x >> 5;
    const int lane = threadIdx.x & 31;
    if (lane == 0) { sA[warp] = tA; sB[warp] = tB; sC[warp] = tC; sE[warp] = tE; }
    __syncthreads();
    if (warp == 0) {
        float rA = (lane < 8) ? sA[lane] : 0.f;
        float rB = (lane < 8) ? sB[lane] : 0.f;
        float rC = (lane < 8) ? sC[lane] : 0.f;
        int   rE = (lane < 8) ? sE[lane] : 0;
#pragma unroll
        for (int off = 4; off > 0; off >>= 1) {
            rA += __shfl_down_sync(0xffffffffu, rA, off);
            rB += __shfl_down_sync(0xffffffffu, rB, off);
            rC += __shfl_down_sync(0xffffffffu, rC, off);
            rE += __shfl_down_sync(0xffffffffu, rE, off);
        }
        if (lane == 0) {
            atomicAdd(&g_accA, (double)rA);
            atomicAdd(&g_accB, (double)rB);
            atomicAdd(&g_accC, (double)rC);
            atomicAdd(&g_accE, (unsigned long long)rE);

            __threadfence();
            unsigned int ticket = atomicAdd(&g_done, 1u);
            if (ticket == (unsigned int)(gridDim.x - 1)) {
                double A = atomicAdd(&g_accA, 0.0);
                double B = atomicAdd(&g_accB, 0.0);
                double C = atomicAdd(&g_accC, 0.0);
                unsigned long long E = atomicAdd(&g_accE, 0ULL);
                const double n = (double)NPIX;
                double s = (double)E / n;
                if (s > 0.2) s = 0.2;
                double total = A + s * (B - (11.0 / 6.0) * C);
                out[0] = (float)(-(total / n));
                g_accA = 0.0; g_accB = 0.0; g_accC = 0.0;
                g_accE = 0ULL; g_done = 0u;
            }
        }
    }
}

extern "C" void kernel_launch(void* const* d_in, const int* in_sizes, int n_in,
                              void* d_out, int out_size) {
    const float* x = (const float*)d_in[0];
    const int* target = (const int*)d_in[1];
    float* out = (float*)d_out;

    ls_edge_kernel<<<NB * (HDIM / TH), 256>>>(target);
    ls_main_kernel<<<NPIX / 4 / 256, 256>>>(x, out);
}

// round 8
// speedup vs baseline: 1.6855x; 1.6855x over previous
#include <cuda_runtime.h>
#include <cuda_bf16.h>
#include <stdint.h>

#define NCLS 6
#define HDIM 512
#define WDIM 512
#define NB   8
#define NPIX (NB * HDIM * WDIM)   // 2097152
#define IMG  (HDIM * WDIM)        // 262144

// Edge kernel tiling: 128 wide x 64 tall tiles.
#define ETW 128
#define ETH 64
#define HALO 5
#define ESH (ETH + 2 * HALO)       // 74 rows in smem
#define ESWB 144                   // 128 + 8 pad each side (aligned int4 loads)
#define EHW 132                    // padded width for hsum array

// Packed per-pixel byte: bits[2:0] = label, bit 3 = edge flag.
__device__ unsigned char g_le[NPIX];
// Global accumulators (zero at module load; finalizing block resets them
// after writing out, so graph replays stay deterministic).
__device__ double g_accA;              // sum over all pixels of lp_label
__device__ double g_accB;              // sum over edge pixels of lp_sum
__device__ double g_accC;              // sum over edge pixels of lp_label
__device__ unsigned long long g_accE;  // edge pixel count
__device__ unsigned int g_done;        // completed-block counter

// Kernel 1: one block per 128x64 tile (256 blocks). Aligned int4 loads packed
// to bytes, 16-wide sliding-window segments (all threads busy), uchar4 stores.
__global__ void __launch_bounds__(256) ls_edge_kernel(const int* __restrict__ target) {
    __shared__ unsigned char sT[ESH][ESWB];  // labels 0..5, cols x0-8 .. x0+135
    __shared__ unsigned char sH[ESH][EHW];   // horizontal 11-window sums (<=55)

    const int bx = blockIdx.x;          // 0 .. 255
    const int b = bx >> 5;              // batch
    const int tile = bx & 31;
    const int y0 = (tile >> 2) * ETH;   // 0,64,...,448
    const int x0 = (tile & 3) * ETW;    // 0,128,256,384
    const int tid = threadIdx.x;
    const int* timg = target + (size_t)b * IMG;

    // Load 74 rows x 36 int4 (cols x0-8 .. x0+135, 16B-aligned since x0%128==0).
    // Zero rows/cols outside the image.
    for (int idx = tid; idx < ESH * 36; idx += 256) {
        const int r = idx / 36;
        const int seg = idx - r * 36;          // int4 index within padded row
        const int gy = y0 + r - HALO;
        const int gx = x0 - 8 + seg * 4;       // aligned
        uchar4 pk = make_uchar4(0, 0, 0, 0);
        if (gy >= 0 && gy < HDIM && gx >= 0 && gx < WDIM) {
            const int4 t = *reinterpret_cast<const int4*>(&timg[gy * WDIM + gx]);
            pk = make_uchar4((unsigned char)t.x, (unsigned char)t.y,
                             (unsigned char)t.z, (unsigned char)t.w);
        }
        *reinterpret_cast<uchar4*>(&sT[r][seg * 4]) = pk;
    }
    __syncthreads();

    // Horizontal sliding sums: 74 rows x 8 segments of 16 outputs = 592 units.
    // Output col c (0..127) window = padded cols c+3 .. c+13.
    for (int u = tid; u < ESH * 8; u += 256) {
        const int r = u >> 3;
        const int c0 = (u & 7) * 16;
        int s = 0;
#pragma unroll
        for (int d = 0; d < 11; d++) s += sT[r][c0 + 3 + d];
        sH[r][c0] = (unsigned char)s;
#pragma unroll
        for (int i = 1; i < 16; i++) {
            s += (int)sT[r][c0 + i + 13] - (int)sT[r][c0 + i + 2];
            sH[r][c0 + i] = (unsigned char)s;
        }
    }
    __syncthreads();

    // Vertical sliding sums + pack: each thread owns two 4x4 patches.
    // Output row i window = sH rows i .. i+10.
    for (int u = tid; u < (ETW / 4) * (ETH / 4); u += 256) {
        const int cg = (u & 31) * 4;
        const int rg = (u >> 5) * 4;
        int S[4];
#pragma unroll
        for (int c = 0; c < 4; c++) {
            int s = 0;
#pragma unroll
            for (int d = 0; d < 11; d++) s += sH[rg + d][cg + c];
            S[c] = s;
        }
        unsigned char* obase = &g_le[(size_t)b * IMG + (y0 + rg) * WDIM + x0 + cg];
#pragma unroll
        for (int i = 0; i < 4; i++) {
            unsigned char pb[4];
#pragma unroll
            for (int c = 0; c < 4; c++) {
                if (i > 0) S[c] += (int)sH[rg + i + 10][cg + c] - (int)sH[rg + i - 1][cg + c];
                const int lab = sT[rg + i + HALO][cg + c + 8];
                pb[c] = (unsigned char)(lab | ((121 * lab != S[c]) ? 8 : 0));
            }
            *reinterpret_cast<uchar4*>(obase + i * WDIM) =
                make_uchar4(pb[0], pb[1], pb[2], pb[3]);
        }
    }
}

// Kernel 2: main (R3-proven shape: 4 px/thread, float4 streaming loads,
// no register cap). Last block finalizes and resets state for graph replay.
__global__ void __launch_bounds__(256) ls_main_kernel(const float* __restrict__ x,
                                                      float* __restrict__ out) {
    const int tix = blockIdx.x * blockDim.x + threadIdx.x;  // 0 .. NPIX/4-1
    const int base = tix << 2;                               // pixel index, mult of 4
    const int b = base >> 18;                                // / 262144
    const int rem = base & (IMG - 1);                        // h*512 + w

    // Packed label|edge bytes (L2-resident from kernel 1).
    const uchar4 le4 = *reinterpret_cast<const uchar4*>(&g_le[base]);
    const unsigned int le[4] = {le4.x, le4.y, le4.z, le4.w};

    // 6 channels x 4 pixels as float4, streaming (read-once data).
    const float* xb = x + (size_t)b * (NCLS * IMG) + rem;
    float v[NCLS][4];
#pragma unroll
    for (int c = 0; c < NCLS; c++) {
        float4 t = __ldcs(reinterpret_cast<const float4*>(&xb[(size_t)c * IMG]));
        v[c][0] = t.x; v[c][1] = t.y; v[c][2] = t.z; v[c][3] = t.w;
    }

    float tA = 0.f, tB = 0.f, tC = 0.f;
    int tE = 0;
#pragma unroll
    for (int j = 0; j < 4; j++) {
        const int lab = (int)(le[j] & 7u);
        // x ~ N(0,1): exp() cannot overflow; skip max-subtraction.
        float se = 0.f, sumx = 0.f, xl = 0.f;
#pragma unroll
        for (int c = 0; c < NCLS; c++) {
            float vc = v[c][j];
            se += __expf(vc);
            sumx += vc;
            xl = (lab == c) ? vc : xl;  // predicated select
        }
        float lse = __logf(se);
        float lpl = xl - lse;            // log_p at the label
        float lps = sumx - 6.0f * lse;   // sum over classes of log_p

        tA += lpl;
        if (le[j] & 8u) { tE++; tB += lps; tC += lpl; }
    }

    // Block reduction
#pragma unroll
    for (int off = 16; off > 0; off >>= 1) {
        tA += __shfl_down_sync(0xffffffffu, tA, off);
        tB += __shfl_down_sync(0xffffffffu, tB, off);
        tC += __shfl_down_sync(0xffffffffu, tC, off);
        tE += __shfl_down_sync(0xffffffffu, tE, off);
    }

    __shared__ float sA[8], sB[8], sC[8];
    __shared__ int sE[8];
    const int warp = threadIdx.x >> 5;
    const int lane = threadIdx.x & 31;
    if (lane == 0) { sA[warp] = tA; sB[warp] = tB; sC[warp] = tC; sE[warp] = tE; }
    __syncthreads();
    if (warp == 0) {
        float rA = (lane < 8) ? sA[lane] : 0.f;
        float rB = (lane < 8) ? sB[lane] : 0.f;
        float rC = (lane < 8) ? sC[lane] : 0.f;
        int   rE = (lane < 8) ? sE[lane] : 0;
#pragma unroll
        for (int off = 4; off > 0; off >>= 1) {
            rA += __shfl_down_sync(0xffffffffu, rA, off);
            rB += __shfl_down_sync(0xffffffffu, rB, off);
            rC += __shfl_down_sync(0xffffffffu, rC, off);
            rE += __shfl_down_sync(0xffffffffu, rE, off);
        }
        if (lane == 0) {
            atomicAdd(&g_accA, (double)rA);
            atomicAdd(&g_accB, (double)rB);
            atomicAdd(&g_accC, (double)rC);
            atomicAdd(&g_accE, (unsigned long long)rE);

            __threadfence();
            unsigned int ticket = atomicAdd(&g_done, 1u);
            if (ticket == (unsigned int)(gridDim.x - 1)) {
                double A = atomicAdd(&g_accA, 0.0);
                double B = atomicAdd(&g_accB, 0.0);
                double C = atomicAdd(&g_accC, 0.0);
                unsigned long long E = atomicAdd(&g_accE, 0ULL);
                const double n = (double)NPIX;
                double s = (double)E / n;
                if (s > 0.2) s = 0.2;
                double total = A + s * (B - (11.0 / 6.0) * C);
                out[0] = (float)(-(total / n));
                g_accA = 0.0; g_accB = 0.0; g_accC = 0.0;
                g_accE = 0ULL; g_done = 0u;
            }
        }
    }
}

extern "C" void kernel_launch(void* const* d_in, const int* in_sizes, int n_in,
                              void* d_out, int out_size) {
    const float* x = (const float*)d_in[0];
    const int* target = (const int*)d_in[1];
    float* out = (float*)d_out;

    ls_edge_kernel<<<NB * 32, 256>>>(target);
    ls_main_kernel<<<NPIX / 4 / 256, 256>>>(x, out);
}